// round 1
// baseline (speedup 1.0000x reference)
#include <cuda_runtime.h>
#include <cstdint>

#define B_   64
#define T_   512
#define E_   512
#define H_   1024
#define G3   3072     // 3*H
#define NCTA 64
#define HC   16       // hidden units per CTA  (NCTA*HC == H_)

// ---------------------------------------------------------------------------
// Device scratch (zero-initialized at module load; no runtime allocation)
// ---------------------------------------------------------------------------
__device__ float    g_xproj[(size_t)B_ * T_ * G3];   // 402 MB input projections
__device__ float    g_h[2][B_][H_];                  // ping-pong hidden state
__device__ unsigned g_cnt;                           // grid barrier counter
__device__ unsigned g_gen;                           // grid barrier generation

// ---------------------------------------------------------------------------
// Helpers
// ---------------------------------------------------------------------------
__device__ __forceinline__ float tf32r(float x) {
    unsigned u;
    asm("cvt.rna.tf32.f32 %0, %1;" : "=r"(u) : "f"(x));
    return __uint_as_float(u);
}

__device__ __forceinline__ void mma_tf32(float c[4], const unsigned a[4],
                                         unsigned b0, unsigned b1) {
    asm volatile(
        "mma.sync.aligned.m16n8k8.row.col.f32.tf32.tf32.f32 "
        "{%0,%1,%2,%3}, {%4,%5,%6,%7}, {%8,%9}, {%0,%1,%2,%3};\n"
        : "+f"(c[0]), "+f"(c[1]), "+f"(c[2]), "+f"(c[3])
        : "r"(a[0]), "r"(a[1]), "r"(a[2]), "r"(a[3]), "r"(b0), "r"(b1));
}

__device__ __forceinline__ float sigf(float x) {
    return 1.0f / (1.0f + __expf(-x));
}

// Software grid barrier over NCTA co-resident CTAs.
__device__ __forceinline__ void grid_sync_dev() {
    __threadfence();
    __syncthreads();
    if (threadIdx.x == 0) {
        volatile unsigned* vg = (volatile unsigned*)&g_gen;
        unsigned my = *vg;
        unsigned a  = atomicAdd(&g_cnt, 1u);
        if (a == NCTA - 1) {
            *((volatile unsigned*)&g_cnt) = 0u;
            __threadfence();
            atomicAdd(&g_gen, 1u);
        } else {
            while (*vg == my) { }
        }
    }
    __syncthreads();
}

// ---------------------------------------------------------------------------
// Phase 1: x_proj[b,t,g] = input[b,t,:] . W_ih[g,:] + b_ih[g]
// TF32 mma GEMM, 128x128 tiles, K=512, double-buffered BK=32.
// grid = (24 n-tiles, 256 m-tiles), 256 threads.
// ---------------------------------------------------------------------------
__global__ void __launch_bounds__(256)
xproj_kernel(const float* __restrict__ A, const float* __restrict__ W,
             const float* __restrict__ bih, const int* __restrict__ seqlen)
{
    const int tm = blockIdx.y, tn = blockIdx.x;
    const int b  = (tm << 7) >> 9;      // (tm*128)/512
    const int t0 = (tm << 7) & 511;
    if (t0 >= seqlen[b]) return;        // whole tile masked; buffer stays zero

    extern __shared__ float smem[];
    float* As = smem;                   // [2][128][36]
    float* Bs = smem + 2 * 128 * 36;    // [2][128][36]

    const int tid  = threadIdx.x;
    const int lane = tid & 31, wid = tid >> 5;
    const int warpM = wid >> 2, warpN = wid & 3;

    const float* Ag = A + (size_t)(tm * 128) * E_;
    const float* Bg = W + (size_t)(tn * 128) * E_;

    float acc[4][4][4];
#pragma unroll
    for (int i = 0; i < 4; i++)
#pragma unroll
        for (int j = 0; j < 4; j++)
#pragma unroll
            for (int k = 0; k < 4; k++) acc[i][j][k] = 0.0f;

    // load first K-tile (ko = 0) into buffer 0
#pragma unroll
    for (int i = 0; i < 4; i++) {
        int f = tid + i * 256;
        int r = f >> 3, c4 = (f & 7) << 2;
        float4 va = *(const float4*)(Ag + (size_t)r * E_ + c4);
        float4 vb = *(const float4*)(Bg + (size_t)r * E_ + c4);
        float* da = As + r * 36 + c4;
        float* db = Bs + r * 36 + c4;
        da[0] = tf32r(va.x); da[1] = tf32r(va.y); da[2] = tf32r(va.z); da[3] = tf32r(va.w);
        db[0] = tf32r(vb.x); db[1] = tf32r(vb.y); db[2] = tf32r(vb.z); db[3] = tf32r(vb.w);
    }
    __syncthreads();

    for (int ko = 0; ko < 16; ko++) {
        float4 pa[4], pb[4];
        if (ko < 15) {
            int kb = (ko + 1) * 32;
#pragma unroll
            for (int i = 0; i < 4; i++) {
                int f = tid + i * 256;
                int r = f >> 3, c4 = (f & 7) << 2;
                pa[i] = *(const float4*)(Ag + (size_t)r * E_ + kb + c4);
                pb[i] = *(const float4*)(Bg + (size_t)r * E_ + kb + c4);
            }
        }
        const float* Ab = As + (ko & 1) * 128 * 36;
        const float* Bb = Bs + (ko & 1) * 128 * 36;
#pragma unroll
        for (int kk = 0; kk < 32; kk += 8) {
            unsigned a[4][4];
            const int kc = kk + (lane & 3);
#pragma unroll
            for (int mt = 0; mt < 4; mt++) {
                int r = warpM * 64 + mt * 16 + (lane >> 2);
                a[mt][0] = __float_as_uint(Ab[r * 36 + kc]);
                a[mt][1] = __float_as_uint(Ab[(r + 8) * 36 + kc]);
                a[mt][2] = __float_as_uint(Ab[r * 36 + kc + 4]);
                a[mt][3] = __float_as_uint(Ab[(r + 8) * 36 + kc + 4]);
            }
#pragma unroll
            for (int nt = 0; nt < 4; nt++) {
                int nr = warpN * 32 + nt * 8 + (lane >> 2);
                unsigned b0 = __float_as_uint(Bb[nr * 36 + kc]);
                unsigned b1 = __float_as_uint(Bb[nr * 36 + kc + 4]);
#pragma unroll
                for (int mt = 0; mt < 4; mt++) mma_tf32(acc[mt][nt], a[mt], b0, b1);
            }
        }
        if (ko < 15) {
            float* Ad = As + ((ko + 1) & 1) * 128 * 36;
            float* Bd = Bs + ((ko + 1) & 1) * 128 * 36;
#pragma unroll
            for (int i = 0; i < 4; i++) {
                int f = tid + i * 256;
                int r = f >> 3, c4 = (f & 7) << 2;
                float* da = Ad + r * 36 + c4;
                float* db = Bd + r * 36 + c4;
                da[0] = tf32r(pa[i].x); da[1] = tf32r(pa[i].y);
                da[2] = tf32r(pa[i].z); da[3] = tf32r(pa[i].w);
                db[0] = tf32r(pb[i].x); db[1] = tf32r(pb[i].y);
                db[2] = tf32r(pb[i].z); db[3] = tf32r(pb[i].w);
            }
        }
        __syncthreads();
    }

    // epilogue: + b_ih, store
#pragma unroll
    for (int nt = 0; nt < 4; nt++) {
        int cg = tn * 128 + warpN * 32 + nt * 8 + 2 * (lane & 3);
        float bv0 = bih[cg], bv1 = bih[cg + 1];
#pragma unroll
        for (int mt = 0; mt < 4; mt++) {
            int rg = tm * 128 + warpM * 64 + mt * 16 + (lane >> 2);
            float2 v0 = make_float2(acc[mt][nt][0] + bv0, acc[mt][nt][1] + bv1);
            float2 v1 = make_float2(acc[mt][nt][2] + bv0, acc[mt][nt][3] + bv1);
            *(float2*)&g_xproj[(size_t)rg * G3 + cg]       = v0;
            *(float2*)&g_xproj[(size_t)(rg + 8) * G3 + cg] = v1;
        }
    }
}

// ---------------------------------------------------------------------------
// Phase 2: persistent recurrent kernel. 64 CTAs x 256 threads, 1 CTA/SM.
// CTA c owns hidden units [c*16, c*16+16): W_hh slice (48x1024) SMEM-resident.
// Per step: GEMM hp = h @ Wslice^T (tf32 mma, h streamed via ld.cg),
// pointwise GRU update, ping-pong write, grid barrier.
// ---------------------------------------------------------------------------
__global__ void __launch_bounds__(256)
gru_kernel(const int* __restrict__ seqlen, const float* __restrict__ W_hh,
           const float* __restrict__ b_hh, const float* __restrict__ W_out,
           const float* __restrict__ b_out, float* __restrict__ out)
{
    extern __shared__ float smem[];
    float* Ws     = smem;                 // [48][1028]  = 49344 floats
    float* hstage = smem + 48 * 1028;     // [2][64][36] = 4608 floats
    float* hp     = hstage;               // reuse as [64][49] after K-loop

    const int c    = blockIdx.x;
    const int tid  = threadIdx.x;
    const int lane = tid & 31, wid = tid >> 5;
    const int mtile = wid >> 1, nhalf = wid & 1;

    // ---- load + tf32-round W_hh slice: local row l = g*16+u  <->  global g*H + c*16 + u
    for (int i = tid; i < 48 * 1024; i += 256) {
        int l = i >> 10, k = i & 1023;
        int g = l >> 4, uu = l & 15;
        Ws[l * 1028 + k] = tf32r(W_hh[(size_t)(g * H_ + c * HC + uu) * H_ + k]);
    }

    // ---- per-thread pointwise assignment: batch b_mine, 4 consecutive units
    const int b_mine = tid >> 2;
    const int ubase  = (tid & 3) << 2;
    const int sl     = seqlen[b_mine];
    float bh[3][4], hprev[4];
#pragma unroll
    for (int g = 0; g < 3; g++)
#pragma unroll
        for (int j = 0; j < 4; j++)
            bh[g][j] = b_hh[g * H_ + c * HC + ubase + j];
#pragma unroll
    for (int j = 0; j < 4; j++) hprev[j] = 0.0f;

    // zero own slice of h buffer 0
    __stcg((float4*)&g_h[0][b_mine][c * HC + ubase], make_float4(0.f, 0.f, 0.f, 0.f));

    grid_sync_dev();

    for (int t = 0; t < T_; t++) {
        const int rb = t & 1, wb = rb ^ 1;

        // stage chunk 0 of h into buffer 0
#pragma unroll
        for (int i = 0; i < 2; i++) {
            int f = tid + i * 256;
            int r = f >> 3, c4 = (f & 7) << 2;
            float4 v = __ldcg((const float4*)&g_h[rb][r][c4]);
            float* d = hstage + r * 36 + c4;
            d[0] = tf32r(v.x); d[1] = tf32r(v.y); d[2] = tf32r(v.z); d[3] = tf32r(v.w);
        }
        __syncthreads();

        float acc[3][4];
#pragma unroll
        for (int nt = 0; nt < 3; nt++)
#pragma unroll
            for (int j = 0; j < 4; j++) acc[nt][j] = 0.0f;

        for (int kc = 0; kc < 32; kc++) {
            float4 p[2];
            if (kc < 31) {
                int kb = (kc + 1) * 32;
#pragma unroll
                for (int i = 0; i < 2; i++) {
                    int f = tid + i * 256;
                    int r = f >> 3, c4 = (f & 7) << 2;
                    p[i] = __ldcg((const float4*)&g_h[rb][r][kb + c4]);
                }
            }
            const float* hsb = hstage + (kc & 1) * 2304;
            const float* Wsb = Ws + kc * 32;
#pragma unroll
            for (int kk = 0; kk < 32; kk += 8) {
                const int kx = kk + (lane & 3);
                const int ar = mtile * 16 + (lane >> 2);
                unsigned av[4];
                av[0] = __float_as_uint(hsb[ar * 36 + kx]);
                av[1] = __float_as_uint(hsb[(ar + 8) * 36 + kx]);
                av[2] = __float_as_uint(hsb[ar * 36 + kx + 4]);
                av[3] = __float_as_uint(hsb[(ar + 8) * 36 + kx + 4]);
#pragma unroll
                for (int nt = 0; nt < 3; nt++) {
                    int nr = nhalf * 24 + nt * 8 + (lane >> 2);
                    unsigned b0 = __float_as_uint(Wsb[nr * 1028 + kx]);
                    unsigned b1 = __float_as_uint(Wsb[nr * 1028 + kx + 4]);
                    mma_tf32(acc[nt], av, b0, b1);
                }
            }
            if (kc < 31) {
                float* dst = hstage + ((kc + 1) & 1) * 2304;
#pragma unroll
                for (int i = 0; i < 2; i++) {
                    int f = tid + i * 256;
                    int r = f >> 3, c4 = (f & 7) << 2;
                    float* d = dst + r * 36 + c4;
                    d[0] = tf32r(p[i].x); d[1] = tf32r(p[i].y);
                    d[2] = tf32r(p[i].z); d[3] = tf32r(p[i].w);
                }
            }
            __syncthreads();
        }

        // dump accumulators to SMEM (hp[b][l], stride 49), aliases hstage
        {
            const int bb = mtile * 16 + (lane >> 2);
#pragma unroll
            for (int nt = 0; nt < 3; nt++) {
                int col = nhalf * 24 + nt * 8 + 2 * (lane & 3);
                hp[bb * 49 + col]           = acc[nt][0];
                hp[bb * 49 + col + 1]       = acc[nt][1];
                hp[(bb + 8) * 49 + col]     = acc[nt][2];
                hp[(bb + 8) * 49 + col + 1] = acc[nt][3];
            }
        }
        __syncthreads();

        // pointwise GRU update for 4 units of batch b_mine
        if (t < sl) {
            size_t base = ((size_t)b_mine * T_ + t) * G3 + c * HC + ubase;
            float4 xr = *(const float4*)&g_xproj[base];
            float4 xz = *(const float4*)&g_xproj[base + H_];
            float4 xn = *(const float4*)&g_xproj[base + 2 * H_];
            const float xrv[4] = {xr.x, xr.y, xr.z, xr.w};
            const float xzv[4] = {xz.x, xz.y, xz.z, xz.w};
            const float xnv[4] = {xn.x, xn.y, xn.z, xn.w};
#pragma unroll
            for (int j = 0; j < 4; j++) {
                float hr = hp[b_mine * 49 + ubase + j];
                float hz = hp[b_mine * 49 + 16 + ubase + j];
                float hn = hp[b_mine * 49 + 32 + ubase + j];
                float r = sigf(xrv[j] + hr + bh[0][j]);
                float z = sigf(xzv[j] + hz + bh[1][j]);
                float n = tanhf(xnv[j] + r * (hn + bh[2][j]));
                hprev[j] = (1.0f - z) * n + z * hprev[j];
            }
        }
        __stcg((float4*)&g_h[wb][b_mine][c * HC + ubase],
               make_float4(hprev[0], hprev[1], hprev[2], hprev[3]));

        grid_sync_dev();
    }

    // ---- output head: CTA c computes batch c. Final h is in g_h[0].
    __syncthreads();
    float s = 0.0f;
    for (int k = tid; k < H_; k += 256)
        s += __ldcg(&g_h[0][c][k]) * W_out[k];
#pragma unroll
    for (int off = 16; off > 0; off >>= 1)
        s += __shfl_xor_sync(0xffffffffu, s, off);
    if (lane == 0) hp[wid] = s;
    __syncthreads();
    if (tid == 0) {
        float tot = 0.0f;
#pragma unroll
        for (int w = 0; w < 8; w++) tot += hp[w];
        out[c] = 1.0f / (1.0f + expf(-(tot + b_out[0])));
    }
}

// ---------------------------------------------------------------------------
// Launch
// ---------------------------------------------------------------------------
extern "C" void kernel_launch(void* const* d_in, const int* in_sizes, int n_in,
                              void* d_out, int out_size)
{
    const float* input  = (const float*)d_in[0];
    const int*   seqlen = (const int*)  d_in[1];
    const float* W_ih   = (const float*)d_in[2];
    const float* W_hh   = (const float*)d_in[3];
    const float* b_ih   = (const float*)d_in[4];
    const float* b_hh   = (const float*)d_in[5];
    const float* W_out  = (const float*)d_in[6];
    const float* b_out  = (const float*)d_in[7];
    float* out = (float*)d_out;

    const int SMEM1 = 2 * 2 * 128 * 36 * (int)sizeof(float);              // 73728 B
    const int SMEM2 = (48 * 1028 + 2 * 64 * 36) * (int)sizeof(float);     // 215808 B

    cudaFuncSetAttribute(xproj_kernel, cudaFuncAttributeMaxDynamicSharedMemorySize, SMEM1);
    cudaFuncSetAttribute(gru_kernel,   cudaFuncAttributeMaxDynamicSharedMemorySize, SMEM2);

    xproj_kernel<<<dim3(24, 256), 256, SMEM1>>>(input, W_ih, b_ih, seqlen);
    gru_kernel<<<NCTA, 256, SMEM2>>>(seqlen, W_hh, b_hh, W_out, b_out, out);
}

// round 3
// speedup vs baseline: 3.4241x; 3.4241x over previous
#include <cuda_runtime.h>
#include <cuda_bf16.h>
#include <cstdint>

#define B_   64
#define T_   512
#define E_   512
#define H_   1024
#define G3   3072
#define NCTA 64
#define HC   16

// Single extern shared symbol for the whole TU (nvcc requires consistent type).
extern __shared__ unsigned char smem_raw[];

// ---------------------------------------------------------------------------
// Device scratch (zero-initialized at load; no runtime allocation)
// ---------------------------------------------------------------------------
__device__ float g_xproj[(size_t)B_ * T_ * G3];                  // input projections
__device__ __align__(128) __nv_bfloat16 g_hb[2][B_][H_];         // ping-pong h (bf16)
__device__ float    g_acc[B_];                                   // head partials
__device__ unsigned g_cnt;                                       // barrier counter
__device__ unsigned g_gen;                                       // barrier generation

// ---------------------------------------------------------------------------
// Helpers
// ---------------------------------------------------------------------------
__device__ __forceinline__ float tf32r(float x) {
    unsigned u;
    asm("cvt.rna.tf32.f32 %0, %1;" : "=r"(u) : "f"(x));
    return __uint_as_float(u);
}

__device__ __forceinline__ void mma_tf32(float c[4], const unsigned a[4],
                                         unsigned b0, unsigned b1) {
    asm volatile(
        "mma.sync.aligned.m16n8k8.row.col.f32.tf32.tf32.f32 "
        "{%0,%1,%2,%3}, {%4,%5,%6,%7}, {%8,%9}, {%0,%1,%2,%3};\n"
        : "+f"(c[0]), "+f"(c[1]), "+f"(c[2]), "+f"(c[3])
        : "r"(a[0]), "r"(a[1]), "r"(a[2]), "r"(a[3]), "r"(b0), "r"(b1));
}

__device__ __forceinline__ void mma_bf16(float* c, unsigned a0, unsigned a1,
                                         unsigned a2, unsigned a3,
                                         unsigned b0, unsigned b1) {
    asm volatile(
        "mma.sync.aligned.m16n8k16.row.col.f32.bf16.bf16.f32 "
        "{%0,%1,%2,%3}, {%4,%5,%6,%7}, {%8,%9}, {%0,%1,%2,%3};\n"
        : "+f"(c[0]), "+f"(c[1]), "+f"(c[2]), "+f"(c[3])
        : "r"(a0), "r"(a1), "r"(a2), "r"(a3), "r"(b0), "r"(b1));
}

__device__ __forceinline__ float sigf(float x) {
    return 1.0f / (1.0f + __expf(-x));
}

__device__ __forceinline__ void grid_sync_dev() {
    __threadfence();
    __syncthreads();
    if (threadIdx.x == 0) {
        volatile unsigned* vg = (volatile unsigned*)&g_gen;
        unsigned my = *vg;
        unsigned a  = atomicAdd(&g_cnt, 1u);
        if (a == NCTA - 1) {
            *((volatile unsigned*)&g_cnt) = 0u;
            __threadfence();
            atomicAdd(&g_gen, 1u);
        } else {
            while (*vg == my) { }
        }
    }
    __syncthreads();
}

// ---------------------------------------------------------------------------
// Phase 1: x_proj = input @ W_ih^T + b_ih   (TF32 mma)
// ---------------------------------------------------------------------------
__global__ void __launch_bounds__(256)
xproj_kernel(const float* __restrict__ A, const float* __restrict__ W,
             const float* __restrict__ bih, const int* __restrict__ seqlen)
{
    const int tm = blockIdx.y, tn = blockIdx.x;
    const int b  = (tm << 7) >> 9;
    const int t0 = (tm << 7) & 511;
    if (t0 >= seqlen[b]) return;

    float* smem = (float*)smem_raw;
    float* As = smem;
    float* Bs = smem + 2 * 128 * 36;

    const int tid  = threadIdx.x;
    const int lane = tid & 31, wid = tid >> 5;
    const int warpM = wid >> 2, warpN = wid & 3;

    const float* Ag = A + (size_t)(tm * 128) * E_;
    const float* Bg = W + (size_t)(tn * 128) * E_;

    float acc[4][4][4];
#pragma unroll
    for (int i = 0; i < 4; i++)
#pragma unroll
        for (int j = 0; j < 4; j++)
#pragma unroll
            for (int k = 0; k < 4; k++) acc[i][j][k] = 0.0f;

#pragma unroll
    for (int i = 0; i < 4; i++) {
        int f = tid + i * 256;
        int r = f >> 3, c4 = (f & 7) << 2;
        float4 va = *(const float4*)(Ag + (size_t)r * E_ + c4);
        float4 vb = *(const float4*)(Bg + (size_t)r * E_ + c4);
        float* da = As + r * 36 + c4;
        float* db = Bs + r * 36 + c4;
        da[0] = tf32r(va.x); da[1] = tf32r(va.y); da[2] = tf32r(va.z); da[3] = tf32r(va.w);
        db[0] = tf32r(vb.x); db[1] = tf32r(vb.y); db[2] = tf32r(vb.z); db[3] = tf32r(vb.w);
    }
    __syncthreads();

    for (int ko = 0; ko < 16; ko++) {
        float4 pa[4], pb[4];
        if (ko < 15) {
            int kb = (ko + 1) * 32;
#pragma unroll
            for (int i = 0; i < 4; i++) {
                int f = tid + i * 256;
                int r = f >> 3, c4 = (f & 7) << 2;
                pa[i] = *(const float4*)(Ag + (size_t)r * E_ + kb + c4);
                pb[i] = *(const float4*)(Bg + (size_t)r * E_ + kb + c4);
            }
        }
        const float* Ab = As + (ko & 1) * 128 * 36;
        const float* Bb = Bs + (ko & 1) * 128 * 36;
#pragma unroll
        for (int kk = 0; kk < 32; kk += 8) {
            unsigned a[4][4];
            const int kc = kk + (lane & 3);
#pragma unroll
            for (int mt = 0; mt < 4; mt++) {
                int r = warpM * 64 + mt * 16 + (lane >> 2);
                a[mt][0] = __float_as_uint(Ab[r * 36 + kc]);
                a[mt][1] = __float_as_uint(Ab[(r + 8) * 36 + kc]);
                a[mt][2] = __float_as_uint(Ab[r * 36 + kc + 4]);
                a[mt][3] = __float_as_uint(Ab[(r + 8) * 36 + kc + 4]);
            }
#pragma unroll
            for (int nt = 0; nt < 4; nt++) {
                int nr = warpN * 32 + nt * 8 + (lane >> 2);
                unsigned b0 = __float_as_uint(Bb[nr * 36 + kc]);
                unsigned b1 = __float_as_uint(Bb[nr * 36 + kc + 4]);
#pragma unroll
                for (int mt = 0; mt < 4; mt++) mma_tf32(acc[mt][nt], a[mt], b0, b1);
            }
        }
        if (ko < 15) {
            float* Ad = As + ((ko + 1) & 1) * 128 * 36;
            float* Bd = Bs + ((ko + 1) & 1) * 128 * 36;
#pragma unroll
            for (int i = 0; i < 4; i++) {
                int f = tid + i * 256;
                int r = f >> 3, c4 = (f & 7) << 2;
                float* da = Ad + r * 36 + c4;
                float* db = Bd + r * 36 + c4;
                da[0] = tf32r(pa[i].x); da[1] = tf32r(pa[i].y);
                da[2] = tf32r(pa[i].z); da[3] = tf32r(pa[i].w);
                db[0] = tf32r(pb[i].x); db[1] = tf32r(pb[i].y);
                db[2] = tf32r(pb[i].z); db[3] = tf32r(pb[i].w);
            }
        }
        __syncthreads();
    }

#pragma unroll
    for (int nt = 0; nt < 4; nt++) {
        int cg = tn * 128 + warpN * 32 + nt * 8 + 2 * (lane & 3);
        float bv0 = bih[cg], bv1 = bih[cg + 1];
#pragma unroll
        for (int mt = 0; mt < 4; mt++) {
            int rg = tm * 128 + warpM * 64 + mt * 16 + (lane >> 2);
            float2 v0 = make_float2(acc[mt][nt][0] + bv0, acc[mt][nt][1] + bv1);
            float2 v1 = make_float2(acc[mt][nt][2] + bv0, acc[mt][nt][3] + bv1);
            *(float2*)&g_xproj[(size_t)rg * G3 + cg]       = v0;
            *(float2*)&g_xproj[(size_t)(rg + 8) * G3 + cg] = v1;
        }
    }
}

// ---------------------------------------------------------------------------
// Phase 2: persistent GRU, 64 CTAs x 256 thr.
// SMEM: W_hh slice in bf16 fragment-order (96KB) + full h (64x1024 bf16,
// 128KB, swizzled). Per step: bulk cp.async h broadcast (2 groups),
// sync-free bf16 mma loop, pointwise in fp32, grid barrier.
// ---------------------------------------------------------------------------
#define WOFF  98304           // bytes of Wbuf region
#define SMEM2 (98304 + 131072)

__global__ void __launch_bounds__(256)
gru_kernel(const int* __restrict__ seqlen, const float* __restrict__ W_hh,
           const float* __restrict__ b_hh, const float* __restrict__ W_out,
           const float* __restrict__ b_out, float* __restrict__ out)
{
    unsigned char* smem = smem_raw;
    uint2* Wbuf = (uint2*)smem;                 // [2][3][64][32] uint2
    float* hp   = (float*)(smem + WOFF);        // alias over h region after mma

    const int c    = blockIdx.x;
    const int tid  = threadIdx.x;
    const int lane = tid & 31, wid = tid >> 5;
    const int mtile = wid >> 1, nhalf = wid & 1;
    const int m0 = mtile * 16;

    const unsigned smem_u32 = (unsigned)__cvta_generic_to_shared(smem);
    const unsigned hs_u32   = smem_u32 + WOFF;

    // ---- pre-permute W_hh slice into B-fragment order (bf16) --------------
    for (int i = tid; i < 12288; i += 256) {
        int nh = i / 6144;
        int r  = i - nh * 6144;
        int nt = r / 2048;
        int r2 = r - nt * 2048;
        int kt = r2 >> 5, li = r2 & 31;
        int o  = nh * 24 + nt * 8 + (li >> 2);
        int grow = (o >> 4) * H_ + c * HC + (o & 15);
        int k0 = kt * 16 + (li & 3) * 2;
        const float* wr = W_hh + (size_t)grow * H_;
        __nv_bfloat162 p0 = __floats2bfloat162_rn(wr[k0],     wr[k0 + 1]);
        __nv_bfloat162 p1 = __floats2bfloat162_rn(wr[k0 + 8], wr[k0 + 9]);
        uint2 v;
        v.x = *reinterpret_cast<unsigned*>(&p0);
        v.y = *reinterpret_cast<unsigned*>(&p1);
        Wbuf[i] = v;
    }

    // ---- pointwise identity: batch b_mine, 4 consecutive units ------------
    const int b_mine = tid >> 2;
    const int ubase  = (tid & 3) << 2;
    const int sl     = seqlen[b_mine];
    float bh[3][4];
#pragma unroll
    for (int g = 0; g < 3; g++)
#pragma unroll
        for (int j = 0; j < 4; j++)
            bh[g][j] = b_hh[g * H_ + c * HC + ubase + j];
    float hv[4] = {0.f, 0.f, 0.f, 0.f};

    // zero my slice of h buffer 0; zero head accumulators
    {
        unsigned long long* p =
            (unsigned long long*)&g_hb[0][b_mine][c * HC + ubase];
        asm volatile("st.global.cg.u64 [%0], 0;" :: "l"(p));
    }
    if (c == 0 && tid < B_) g_acc[tid] = 0.f;

    grid_sync_dev();

    // ---- per-lane compute constants ----------------------------------------
    const int      arow  = m0 + (lane & 15);
    const unsigned arowa = hs_u32 + arow * 2048;
    const unsigned klo   = (lane >> 4) << 4;
    const unsigned aswz  = (arow & 7) << 4;
    const unsigned wbase = smem_u32 + (unsigned)((nhalf * 3 * 64) * 256 + lane * 8);

    for (int t = 0; t < T_; t++) {
        const int rb = t & 1, wbuf_i = rb ^ 1;

        // ---- bulk cp.async h broadcast: 2 halves x 16 chunks of 16B -------
        const unsigned char* hsrc = (const unsigned char*)&g_hb[rb][0][0];
#pragma unroll
        for (int half = 0; half < 2; half++) {
#pragma unroll
            for (int i = 0; i < 16; i++) {
                int j   = tid + i * 256;
                int row = j >> 6;
                int kb  = half * 1024 + ((j & 63) << 4);
                unsigned dst = hs_u32 + row * 2048 + (kb ^ ((row & 7) << 4));
                const void* src = hsrc + row * 2048 + kb;
                asm volatile("cp.async.cg.shared.global [%0], [%1], 16;\n"
                             :: "r"(dst), "l"(src));
            }
            asm volatile("cp.async.commit_group;\n");
        }

        // ---- xproj loads (DRAM, independent of h) --------------------------
        const bool active = t < sl;
        float4 xr, xz, xn;
        if (active) {
            size_t base = ((size_t)b_mine * T_ + t) * G3 + c * HC + ubase;
            xr = __ldcg((const float4*)&g_xproj[base]);
            xz = __ldcg((const float4*)&g_xproj[base + H_]);
            xn = __ldcg((const float4*)&g_xproj[base + 2 * H_]);
        }

        float acc[2][3][4];
#pragma unroll
        for (int p = 0; p < 2; p++)
#pragma unroll
            for (int nt = 0; nt < 3; nt++)
#pragma unroll
                for (int j = 0; j < 4; j++) acc[p][nt][j] = 0.f;

        // ---- K loop: 2 halves of 32 kt, sync-free inside ------------------
#pragma unroll
        for (int half = 0; half < 2; half++) {
            if (half == 0) asm volatile("cp.async.wait_group 1;\n" ::: "memory");
            else           asm volatile("cp.async.wait_group 0;\n" ::: "memory");
            __syncthreads();
#pragma unroll
            for (int kt = half * 32; kt < half * 32 + 32; kt++) {
                unsigned a0, a1, a2, a3;
                unsigned addr = arowa + ((((unsigned)kt << 5) + klo) ^ aswz);
                asm volatile(
                    "ldmatrix.sync.aligned.m8n8.x4.shared.b16 {%0,%1,%2,%3}, [%4];\n"
                    : "=r"(a0), "=r"(a1), "=r"(a2), "=r"(a3) : "r"(addr));
                unsigned b00, b01, b10, b11, b20, b21;
                asm volatile("ld.shared.v2.u32 {%0,%1}, [%2];\n"
                             : "=r"(b00), "=r"(b01) : "r"(wbase + (0 * 64 + kt) * 256));
                asm volatile("ld.shared.v2.u32 {%0,%1}, [%2];\n"
                             : "=r"(b10), "=r"(b11) : "r"(wbase + (1 * 64 + kt) * 256));
                asm volatile("ld.shared.v2.u32 {%0,%1}, [%2];\n"
                             : "=r"(b20), "=r"(b21) : "r"(wbase + (2 * 64 + kt) * 256));
                const int p = kt & 1;
                mma_bf16(acc[p][0], a0, a1, a2, a3, b00, b01);
                mma_bf16(acc[p][1], a0, a1, a2, a3, b10, b11);
                mma_bf16(acc[p][2], a0, a1, a2, a3, b20, b21);
            }
        }
        __syncthreads();   // h reads done; hp alias region now safe

        // ---- dump accumulators to hp[b][o] (stride 52) ---------------------
        {
            int bb = m0 + (lane >> 2);
#pragma unroll
            for (int nt = 0; nt < 3; nt++) {
                int col = nhalf * 24 + nt * 8 + ((lane & 3) << 1);
                hp[bb * 52 + col]           = acc[0][nt][0] + acc[1][nt][0];
                hp[bb * 52 + col + 1]       = acc[0][nt][1] + acc[1][nt][1];
                hp[(bb + 8) * 52 + col]     = acc[0][nt][2] + acc[1][nt][2];
                hp[(bb + 8) * 52 + col + 1] = acc[0][nt][3] + acc[1][nt][3];
            }
        }
        __syncthreads();

        // ---- pointwise GRU update (fp32 carry) ------------------------------
        if (active) {
            const float xrv[4] = {xr.x, xr.y, xr.z, xr.w};
            const float xzv[4] = {xz.x, xz.y, xz.z, xz.w};
            const float xnv[4] = {xn.x, xn.y, xn.z, xn.w};
#pragma unroll
            for (int j = 0; j < 4; j++) {
                float hr = hp[b_mine * 52 + ubase + j];
                float hz = hp[b_mine * 52 + 16 + ubase + j];
                float hn = hp[b_mine * 52 + 32 + ubase + j];
                float r = sigf(xrv[j] + hr + bh[0][j]);
                float z = sigf(xzv[j] + hz + bh[1][j]);
                float n = tanhf(xnv[j] + r * (hn + bh[2][j]));
                hv[j] = (1.0f - z) * n + z * hv[j];
            }
        }
        // write h (bf16) for next step's GEMM
        {
            __nv_bfloat162 w0 = __floats2bfloat162_rn(hv[0], hv[1]);
            __nv_bfloat162 w1 = __floats2bfloat162_rn(hv[2], hv[3]);
            unsigned u0 = *reinterpret_cast<unsigned*>(&w0);
            unsigned u1 = *reinterpret_cast<unsigned*>(&w1);
            unsigned long long* p =
                (unsigned long long*)&g_hb[wbuf_i][b_mine][c * HC + ubase];
            asm volatile("st.global.cg.v2.u32 [%0], {%1,%2};\n"
                         :: "l"(p), "r"(u0), "r"(u1));
        }

        grid_sync_dev();
    }

    // ---- head: out[b] = sigmoid(h[b] . W_out + b_out) ----------------------
    float part = 0.f;
#pragma unroll
    for (int j = 0; j < 4; j++)
        part += hv[j] * W_out[c * HC + ubase + j];
    part += __shfl_down_sync(0xffffffffu, part, 1);
    part += __shfl_down_sync(0xffffffffu, part, 2);
    if ((tid & 3) == 0) atomicAdd(&g_acc[b_mine], part);

    grid_sync_dev();

    if (c == 0 && tid < B_)
        out[tid] = 1.0f / (1.0f + expf(-(g_acc[tid] + b_out[0])));
}

// ---------------------------------------------------------------------------
// Launch
// ---------------------------------------------------------------------------
extern "C" void kernel_launch(void* const* d_in, const int* in_sizes, int n_in,
                              void* d_out, int out_size)
{
    const float* input  = (const float*)d_in[0];
    const int*   seqlen = (const int*)  d_in[1];
    const float* W_ih   = (const float*)d_in[2];
    const float* W_hh   = (const float*)d_in[3];
    const float* b_ih   = (const float*)d_in[4];
    const float* b_hh   = (const float*)d_in[5];
    const float* W_out  = (const float*)d_in[6];
    const float* b_out  = (const float*)d_in[7];
    float* out = (float*)d_out;

    const int SMEM1 = 2 * 2 * 128 * 36 * (int)sizeof(float);   // 73728 B

    cudaFuncSetAttribute(xproj_kernel, cudaFuncAttributeMaxDynamicSharedMemorySize, SMEM1);
    cudaFuncSetAttribute(gru_kernel,   cudaFuncAttributeMaxDynamicSharedMemorySize, SMEM2);

    xproj_kernel<<<dim3(24, 256), 256, SMEM1>>>(input, W_ih, b_ih, seqlen);
    gru_kernel<<<NCTA, 256, SMEM2>>>(seqlen, W_hh, b_hh, W_out, b_out, out);
}